// round 4
// baseline (speedup 1.0000x reference)
#include <cuda_runtime.h>
#include <cuda_bf16.h>

// Distral multi-head tiny MLP (N = 32769 heads), pure HBM-bound (~120MB once).
// R4: per-warp float4 staging. Each warp loads its head's 900 params as 8
// LDG.128/lane (coalesced 512B bursts), stores to a private smem slice,
// __syncwarp only (no block barrier), then computes with the R1 pattern.
// Per-warp smem layout: [0,300) W1 | [300,400) b1 | [400,900) W2.

#define HID 100
#define OUT 5
#define HPB 8
#define THREADS 256
#define PW 912   // per-warp smem floats (900 rounded up, keeps 16B alignment)

__global__ __launch_bounds__(THREADS) void distral_kernel(
    const float* __restrict__ x,
    const float* __restrict__ W1,
    const float* __restrict__ b1,
    const float* __restrict__ W2,
    const float* __restrict__ b2,
    float* __restrict__ out,
    int n_heads)
{
    __shared__ float smem[HPB * PW];   // 29184 B

    const int tid  = threadIdx.x;
    const int w    = tid >> 5;
    const int lane = tid & 31;
    const int head = blockIdx.x * HPB + w;
    if (head >= n_heads) return;

    float* sw = smem + w * PW;

    const float4* g1 = (const float4*)(W1 + (size_t)head * (HID * 3)); // 75 vec4
    const float4* gb = (const float4*)(b1 + (size_t)head * HID);       // 25 vec4
    const float4* g2 = (const float4*)(W2 + (size_t)head * (OUT * HID)); // 125 vec4

    // ---- front-batched vector load burst (8 LDG.128 per lane, predicated tails)
    const float4 z = make_float4(0.f, 0.f, 0.f, 0.f);
    float4 r1a = g1[lane];
    float4 r1b = g1[lane + 32];
    float4 r1c = (lane < 11) ? g1[lane + 64] : z;
    float4 rb  = (lane < 25) ? gb[lane]      : z;
    float4 r2a = g2[lane];
    float4 r2b = g2[lane + 32];
    float4 r2c = g2[lane + 64];
    float4 r2d = (lane < 29) ? g2[lane + 96] : z;

    float4* s1 = (float4*)(sw);          // W1: 75 vec4
    float4* sb = (float4*)(sw + 300);    // b1: 25 vec4
    float4* s2 = (float4*)(sw + 400);    // W2: 125 vec4

    s1[lane]      = r1a;
    s1[lane + 32] = r1b;
    if (lane < 11) s1[lane + 64] = r1c;
    if (lane < 25) sb[lane]      = rb;
    s2[lane]      = r2a;
    s2[lane + 32] = r2b;
    s2[lane + 64] = r2c;
    if (lane < 29) s2[lane + 96] = r2d;

    __syncwarp();

    // ---- compute from smem (R1 ownership: lane covers j = lane + 32m) ----
    const float x0 = __ldg(x + (size_t)head * 3 + 0);
    const float x1 = __ldg(x + (size_t)head * 3 + 1);
    const float x2 = __ldg(x + (size_t)head * 3 + 2);

    float h[4];
    #pragma unroll
    for (int m = 0; m < 4; m++) {
        int j = lane + 32 * m;
        if (j < HID) {
            float v = fmaf(sw[j * 3 + 0], x0,
                      fmaf(sw[j * 3 + 1], x1,
                      fmaf(sw[j * 3 + 2], x2, sw[300 + j])));
            h[m] = fmaxf(v, 0.0f);
        } else {
            h[m] = 0.0f;
        }
    }

    float logits[OUT];
    #pragma unroll
    for (int o = 0; o < OUT; o++) {
        float p = 0.0f;
        #pragma unroll
        for (int m = 0; m < 4; m++) {
            int j = lane + 32 * m;
            if (j < HID) p = fmaf(sw[400 + o * HID + j], h[m], p);
        }
        #pragma unroll
        for (int s = 16; s; s >>= 1)
            p += __shfl_xor_sync(0xffffffffu, p, s);
        logits[o] = p + __ldg(b2 + (size_t)head * OUT + o);
    }

    float mx = logits[0];
    #pragma unroll
    for (int o = 1; o < OUT; o++) mx = fmaxf(mx, logits[o]);
    float e[OUT], sum = 0.0f;
    #pragma unroll
    for (int o = 0; o < OUT; o++) { e[o] = __expf(logits[o] - mx); sum += e[o]; }
    float inv = __frcp_rn(sum);

    if (lane < OUT)
        out[(size_t)head * OUT + lane] = e[lane] * inv;
}

extern "C" void kernel_launch(void* const* d_in, const int* in_sizes, int n_in,
                              void* d_out, int out_size)
{
    const float* x  = (const float*)d_in[0];
    const float* W1 = (const float*)d_in[1];
    const float* b1 = (const float*)d_in[2];
    const float* W2 = (const float*)d_in[3];
    const float* b2 = (const float*)d_in[4];
    float* out = (float*)d_out;

    int n_heads = in_sizes[0] / 3;   // x is (N, 3)
    int blocks = (n_heads + HPB - 1) / HPB;

    distral_kernel<<<blocks, THREADS>>>(x, W1, b1, W2, b2, out, n_heads);
}